// round 1
// baseline (speedup 1.0000x reference)
#include <cuda_runtime.h>
#include <stdint.h>

// Problem constants
#define B_IMGS   64
#define HW       384
#define IMG_ELEMS (HW * HW)              // 147456
#define N_TOTAL  (B_IMGS * IMG_ELEMS)    // 9437184
#define WIN      7
#define PAD      3
#define NP       49
#define COV_NORM (49.0f / 48.0f)
#define OUT_DIM  378                      // 384 - 2*PAD
#define N_OUT    (64.0 * 378.0 * 378.0)   // 9144576

// Tile config for SSIM kernel
#define TILE     32                       // 32x32 output tile
#define IN_T     38                       // TILE + 6
#define IN_STRIDE 39                      // odd stride -> conflict-free
#define HS_STRIDE 33
#define NTILES   12                       // ceil(378/32)

__device__ double       g_sum;
__device__ unsigned int g_maxbits;

// ---------------------------------------------------------------------------
__global__ void init_kernel() {
    g_sum = 0.0;
    g_maxbits = 0u;   // gt values are >= 0
}

// ---------------------------------------------------------------------------
__global__ void max_kernel(const float* __restrict__ gt) {
    const float4* v = reinterpret_cast<const float4*>(gt);
    int n4 = N_TOTAL / 4;
    float m = 0.0f;
    for (int i = blockIdx.x * blockDim.x + threadIdx.x; i < n4;
         i += gridDim.x * blockDim.x) {
        float4 x = v[i];
        m = fmaxf(m, fmaxf(fmaxf(x.x, x.y), fmaxf(x.z, x.w)));
    }
    // warp reduce
    #pragma unroll
    for (int o = 16; o; o >>= 1) m = fmaxf(m, __shfl_xor_sync(0xffffffffu, m, o));
    __shared__ float smax[32];
    int lane = threadIdx.x & 31, wid = threadIdx.x >> 5;
    if (lane == 0) smax[wid] = m;
    __syncthreads();
    if (wid == 0) {
        int nw = blockDim.x >> 5;
        m = (lane < nw) ? smax[lane] : 0.0f;
        #pragma unroll
        for (int o = 16; o; o >>= 1) m = fmaxf(m, __shfl_xor_sync(0xffffffffu, m, o));
        if (lane == 0) atomicMax(&g_maxbits, __float_as_uint(m));
    }
}

// ---------------------------------------------------------------------------
// One block computes a 32x32 tile of interior SSIM outputs for one image.
// Separable 7x7 box sums via horizontal running sums (shared) + vertical
// running sums (registers).
__global__ __launch_bounds__(256, 4)
void ssim_kernel(const float* __restrict__ gt, const float* __restrict__ pred) {
    __shared__ float sg[IN_T * IN_STRIDE];
    __shared__ float sp[IN_T * IN_STRIDE];
    __shared__ float hs[5][IN_T * HS_STRIDE];
    __shared__ float sred[256];

    const int img = blockIdx.z;
    const int bx  = blockIdx.x;
    const int by  = blockIdx.y;
    const int tid = threadIdx.x;

    const float* gbase = gt   + img * IMG_ELEMS;
    const float* pbase = pred + img * IMG_ELEMS;

    // input region origin (row0/col0 map to input row index 0 of the tile)
    const int row0 = by * TILE;   // = (y0 - 3) where y0 = 3 + by*32
    const int col0 = bx * TILE;

    // ---- Phase 1: load 38x38 gt & pred tiles (clamped at image edge) ----
    for (int i = tid; i < IN_T * IN_T; i += 256) {
        int r = i / IN_T;
        int c = i - r * IN_T;
        int gy = row0 + r; if (gy > HW - 1) gy = HW - 1;
        int gx = col0 + c; if (gx > HW - 1) gx = HW - 1;
        int gidx = gy * HW + gx;
        sg[r * IN_STRIDE + c] = gbase[gidx];
        sp[r * IN_STRIDE + c] = pbase[gidx];
    }
    __syncthreads();

    // ---- Phase 2: horizontal 7-tap running sums for 5 channels ----
    // work item: (row r in 0..37, segment s in 0..3 of 8 output cols)
    if (tid < IN_T * 4) {
        int r  = tid >> 2;
        int s  = tid & 3;
        int c0 = s * 8;
        float gv[14], pv[14];
        const float* grow = &sg[r * IN_STRIDE + c0];
        const float* prow = &sp[r * IN_STRIDE + c0];
        #pragma unroll
        for (int i = 0; i < 14; i++) { gv[i] = grow[i]; pv[i] = prow[i]; }
        float a0 = 0.f, a1 = 0.f, a2 = 0.f, a3 = 0.f, a4 = 0.f;
        #pragma unroll
        for (int i = 0; i < 7; i++) {
            a0 += gv[i]; a1 += pv[i];
            a2 = fmaf(gv[i], gv[i], a2);
            a3 = fmaf(pv[i], pv[i], a3);
            a4 = fmaf(gv[i], pv[i], a4);
        }
        int base = r * HS_STRIDE + c0;
        hs[0][base] = a0; hs[1][base] = a1; hs[2][base] = a2;
        hs[3][base] = a3; hs[4][base] = a4;
        #pragma unroll
        for (int k = 1; k < 8; k++) {
            float ga = gv[6 + k], pa = pv[6 + k];
            float gs = gv[k - 1], ps = pv[k - 1];
            a0 += ga - gs;
            a1 += pa - ps;
            a2 += ga * ga - gs * gs;
            a3 += pa * pa - ps * ps;
            a4 += ga * pa - gs * ps;
            hs[0][base + k] = a0; hs[1][base + k] = a1; hs[2][base + k] = a2;
            hs[3][base + k] = a3; hs[4][base + k] = a4;
        }
    }
    __syncthreads();

    // ---- Phase 3: vertical 7-tap running sums + SSIM ----
    const float R  = __uint_as_float(g_maxbits);      // data_range = max(gt)
    const float C1 = (0.01f * R) * (0.01f * R);
    const float C2 = (0.03f * R) * (0.03f * R);
    const float inv = 1.0f / 49.0f;

    const int tx = tid & 31;        // output column within tile
    const int ty = tid >> 5;        // 0..7 -> 4 output rows each
    const int jbase = ty * 4;

    const int ox = 3 + col0 + tx;   // absolute output x
    float local = 0.0f;

    float s0 = 0.f, s1 = 0.f, s2 = 0.f, s3 = 0.f, s4 = 0.f;
    #pragma unroll
    for (int r = 0; r < 7; r++) {
        int idx = (jbase + r) * HS_STRIDE + tx;
        s0 += hs[0][idx]; s1 += hs[1][idx]; s2 += hs[2][idx];
        s3 += hs[3][idx]; s4 += hs[4][idx];
    }
    #pragma unroll
    for (int k = 0; k < 4; k++) {
        if (k > 0) {
            int ia = (jbase + 6 + k) * HS_STRIDE + tx;
            int is = (jbase + k - 1) * HS_STRIDE + tx;
            s0 += hs[0][ia] - hs[0][is];
            s1 += hs[1][ia] - hs[1][is];
            s2 += hs[2][ia] - hs[2][is];
            s3 += hs[3][ia] - hs[3][is];
            s4 += hs[4][ia] - hs[4][is];
        }
        int oy = 3 + row0 + jbase + k;
        if (ox <= HW - 1 - PAD && oy <= HW - 1 - PAD) {
            float ux = s0 * inv, uy = s1 * inv;
            float uxx = s2 * inv - ux * ux;
            float uyy = s3 * inv - uy * uy;
            float uxy = s4 * inv - ux * uy;
            float vx = COV_NORM * uxx, vy = COV_NORM * uyy, vxy = COV_NORM * uxy;
            float num = (2.0f * ux * uy + C1) * (2.0f * vxy + C2);
            float den = (ux * ux + uy * uy + C1) * (vx + vy + C2);
            local += num / den;
        }
    }

    // ---- block reduce + global accumulate ----
    sred[tid] = local;
    __syncthreads();
    for (int s = 128; s >= 32; s >>= 1) {
        if (tid < s) sred[tid] += sred[tid + s];
        __syncthreads();
    }
    if (tid < 32) {
        float v = sred[tid];
        #pragma unroll
        for (int o = 16; o; o >>= 1) v += __shfl_xor_sync(0xffffffffu, v, o);
        if (tid == 0) atomicAdd(&g_sum, (double)v);
    }
}

// ---------------------------------------------------------------------------
__global__ void finalize_kernel(float* __restrict__ out) {
    out[0] = (float)(g_sum / N_OUT);
}

// ---------------------------------------------------------------------------
extern "C" void kernel_launch(void* const* d_in, const int* in_sizes, int n_in,
                              void* d_out, int out_size) {
    const float* gt   = (const float*)d_in[0];
    const float* pred = (const float*)d_in[1];
    // d_in[2] = window (uniform 1/49, constant by construction) -- unused
    float* out = (float*)d_out;

    init_kernel<<<1, 1>>>();
    max_kernel<<<2048, 256>>>(gt);
    dim3 grid(NTILES, NTILES, B_IMGS);
    ssim_kernel<<<grid, 256>>>(gt, pred);
    finalize_kernel<<<1, 1>>>(out);
}

// round 2
// speedup vs baseline: 1.7820x; 1.7820x over previous
#include <cuda_runtime.h>
#include <stdint.h>

#define B_IMGS    64
#define HW        384
#define IMG_ELEMS (HW * HW)
#define N_TOTAL   (B_IMGS * IMG_ELEMS)
#define PAD       3
#define COV_NORM  (49.0f / 48.0f)
#define N_OUT     (64.0 * 378.0 * 378.0)

// ssim tile: 64 output cols x 32 output rows, input 70 cols x 38 rows
#define TW        64
#define TH        32
#define IN_W      70
#define VS_STRIDE 71          // 71 mod 32 = 7, gcd(7,32)=1 -> conflict-free
#define GX_TILES  6           // ceil(378/64)
#define GY_TILES  12          // ceil(378/32)
#define NBLOCKS   (GX_TILES * GY_TILES * B_IMGS)   // 4608

#define MAX_BLOCKS 256

__device__ double       g_sum;
__device__ unsigned int g_ticket;
__device__ float        g_blockmax[MAX_BLOCKS];

// ---------------------------------------------------------------------------
// Kernel 1: per-block partial max of gt (+ zero the accumulators).
__global__ __launch_bounds__(256)
void prep_kernel(const float* __restrict__ gt) {
    if (blockIdx.x == 0 && threadIdx.x == 0) { g_sum = 0.0; g_ticket = 0u; }

    const float4* v = reinterpret_cast<const float4*>(gt);
    const int n4 = N_TOTAL / 4;
    float m = 0.0f;
    for (int i = blockIdx.x * 256 + threadIdx.x; i < n4; i += MAX_BLOCKS * 256) {
        float4 x = v[i];
        m = fmaxf(m, fmaxf(fmaxf(x.x, x.y), fmaxf(x.z, x.w)));
    }
    #pragma unroll
    for (int o = 16; o; o >>= 1) m = fmaxf(m, __shfl_xor_sync(0xffffffffu, m, o));
    __shared__ float smax[8];
    int lane = threadIdx.x & 31, wid = threadIdx.x >> 5;
    if (lane == 0) smax[wid] = m;
    __syncthreads();
    if (wid == 0) {
        m = (lane < 8) ? smax[lane] : 0.0f;
        #pragma unroll
        for (int o = 4; o; o >>= 1) m = fmaxf(m, __shfl_xor_sync(0xffffffffu, m, o));
        if (lane == 0) g_blockmax[blockIdx.x] = m;
    }
}

// ---------------------------------------------------------------------------
// Kernel 2: fused SSIM. Vertical-first separable 7x7 box sums.
// Phase A: threads own input columns, stream rows from global with a 7-row
//          rolling register window; write 5 vertical sums per output row to
//          shared (raw pixels never hit smem).
// Phase B: threads own (row, 8-col segment); 7-col rolling register window
//          over the vertical sums; SSIM math in registers.
__global__ __launch_bounds__(256, 4)
void ssim_kernel(const float* __restrict__ gt, const float* __restrict__ pred,
                 float* __restrict__ out) {
    __shared__ float vs[5][TH * VS_STRIDE];
    __shared__ float sred[256];
    __shared__ float smaxv;

    const int tid = threadIdx.x;
    const int bx = blockIdx.x, by = blockIdx.y, img = blockIdx.z;

    const float* gbase = gt   + img * IMG_ELEMS;
    const float* pbase = pred + img * IMG_ELEMS;

    // ---- Phase A ----
    if (tid >= 224) {
        // warp 7 (idle in phase A): finish the global max reduction
        int lane = tid - 224;
        float m = 0.0f;
        #pragma unroll
        for (int i = 0; i < MAX_BLOCKS / 32; i++)
            m = fmaxf(m, g_blockmax[lane + 32 * i]);
        #pragma unroll
        for (int o = 16; o; o >>= 1) m = fmaxf(m, __shfl_xor_sync(0xffffffffu, m, o));
        if (lane == 0) smaxv = m;
    } else if (tid < 2 * IN_W) {
        const int h = (tid < IN_W) ? 0 : 1;          // row-half
        const int c = tid - h * IN_W;                // input column in tile
        const int gx = min(bx * TW + c, HW - 1);
        const int rb = by * TH + h * 16;             // input row base
        const float* gp = gbase + gx;
        const float* pp = pbase + gx;

        float g[7], p[7];
        float s0 = 0.f, s1 = 0.f, s2 = 0.f, s3 = 0.f, s4 = 0.f;
        #pragma unroll
        for (int i = 0; i < 6; i++) {
            int gy = min(rb + i, HW - 1);
            float a = __ldg(gp + gy * HW);
            float b = __ldg(pp + gy * HW);
            g[i] = a; p[i] = b;
            s0 += a; s1 += b;
            s2 = fmaf(a, a, s2); s3 = fmaf(b, b, s3); s4 = fmaf(a, b, s4);
        }
        const int orow = h * 16;
        #pragma unroll
        for (int j = 0; j < 16; j++) {
            int slot = (6 + j) % 7;
            int gy = min(rb + 6 + j, HW - 1);
            float a = __ldg(gp + gy * HW);
            float b = __ldg(pp + gy * HW);
            g[slot] = a; p[slot] = b;
            s0 += a; s1 += b;
            s2 = fmaf(a, a, s2); s3 = fmaf(b, b, s3); s4 = fmaf(a, b, s4);
            int o = (orow + j) * VS_STRIDE + c;
            vs[0][o] = s0; vs[1][o] = s1; vs[2][o] = s2; vs[3][o] = s3; vs[4][o] = s4;
            int os = j % 7;
            float ga = g[os], pa = p[os];
            s0 -= ga; s1 -= pa;
            s2 -= ga * ga; s3 -= pa * pa; s4 -= ga * pa;
        }
    }
    __syncthreads();

    // ---- Phase B ----
    const float R  = smaxv;
    const float C1 = (0.01f * R) * (0.01f * R);
    const float C2 = (0.03f * R) * (0.03f * R);
    const float inv = 1.0f / 49.0f;

    const int seg = tid >> 5;          // 0..7
    const int row = tid & 31;          // 0..31
    const int base = row * VS_STRIDE + seg * 8;

    const int oy = PAD + by * TH + row;
    const bool rowvalid = (oy <= HW - 1 - PAD);
    const int ox0 = PAD + bx * TW + seg * 8;

    float w0[7], w1[7], w2[7], w3[7], w4[7];
    float s0 = 0.f, s1 = 0.f, s2 = 0.f, s3 = 0.f, s4 = 0.f;
    #pragma unroll
    for (int i = 0; i < 6; i++) {
        w0[i] = vs[0][base + i]; w1[i] = vs[1][base + i]; w2[i] = vs[2][base + i];
        w3[i] = vs[3][base + i]; w4[i] = vs[4][base + i];
        s0 += w0[i]; s1 += w1[i]; s2 += w2[i]; s3 += w3[i]; s4 += w4[i];
    }

    float local = 0.0f;
    #pragma unroll
    for (int k = 0; k < 8; k++) {
        int slot = (6 + k) % 7;
        w0[slot] = vs[0][base + 6 + k]; s0 += w0[slot];
        w1[slot] = vs[1][base + 6 + k]; s1 += w1[slot];
        w2[slot] = vs[2][base + 6 + k]; s2 += w2[slot];
        w3[slot] = vs[3][base + 6 + k]; s3 += w3[slot];
        w4[slot] = vs[4][base + 6 + k]; s4 += w4[slot];

        if (rowvalid && (ox0 + k) <= HW - 1 - PAD) {
            float ux = s0 * inv, uy = s1 * inv;
            float uxx = s2 * inv - ux * ux;
            float uyy = s3 * inv - uy * uy;
            float uxy = s4 * inv - ux * uy;
            float vx = COV_NORM * uxx, vy = COV_NORM * uyy, vxy = COV_NORM * uxy;
            float num = (2.0f * ux * uy + C1) * (2.0f * vxy + C2);
            float den = (ux * ux + uy * uy + C1) * (vx + vy + C2);
            local += __fdividef(num, den);
        }

        int os = k % 7;
        s0 -= w0[os]; s1 -= w1[os]; s2 -= w2[os]; s3 -= w3[os]; s4 -= w4[os];
    }

    // ---- block reduce + global accumulate + last-block finalize ----
    sred[tid] = local;
    __syncthreads();
    #pragma unroll
    for (int s = 128; s >= 32; s >>= 1) {
        if (tid < s) sred[tid] += sred[tid + s];
        __syncthreads();
    }
    if (tid < 32) {
        float v = sred[tid];
        #pragma unroll
        for (int o = 16; o; o >>= 1) v += __shfl_xor_sync(0xffffffffu, v, o);
        if (tid == 0) {
            atomicAdd(&g_sum, (double)v);
            __threadfence();
            unsigned t = atomicAdd(&g_ticket, 1u);
            if (t == NBLOCKS - 1) {
                double total = atomicAdd(&g_sum, 0.0);   // coherent read
                out[0] = (float)(total / N_OUT);
            }
        }
    }
}

// ---------------------------------------------------------------------------
extern "C" void kernel_launch(void* const* d_in, const int* in_sizes, int n_in,
                              void* d_out, int out_size) {
    const float* gt   = (const float*)d_in[0];
    const float* pred = (const float*)d_in[1];
    float* out = (float*)d_out;

    prep_kernel<<<MAX_BLOCKS, 256>>>(gt);
    dim3 grid(GX_TILES, GY_TILES, B_IMGS);
    ssim_kernel<<<grid, 256>>>(gt, pred, out);
}

// round 3
// speedup vs baseline: 1.8371x; 1.0309x over previous
#include <cuda_runtime.h>
#include <stdint.h>

#define B_IMGS    64
#define HW        384
#define IMG_ELEMS (HW * HW)
#define N_TOTAL   (B_IMGS * IMG_ELEMS)
#define PAD       3
#define COV_NORM  (49.0f / 48.0f)
#define N_OUT     (64.0 * 378.0 * 378.0)

// ssim tile: 64 output cols x 32 output rows, input 70 cols x 38 rows
#define TW        64
#define TH        32
#define IN_W      70
#define AOS_STRIDE 71   // float4 units; 28*row mod 32 distinct per 8 lanes -> LDS.128 conflict-free
#define S4_STRIDE  77   // floats; 13*row mod 32, gcd(13,32)=1 -> conflict-free
#define GX_TILES  6
#define GY_TILES  12
#define NBLOCKS   (GX_TILES * GY_TILES * B_IMGS)

#define MAX_BLOCKS 256

__device__ double       g_sum;
__device__ unsigned int g_ticket;
__device__ float        g_blockmax[MAX_BLOCKS];

// ---------------------------------------------------------------------------
__global__ __launch_bounds__(256)
void prep_kernel(const float* __restrict__ gt) {
    if (blockIdx.x == 0 && threadIdx.x == 0) { g_sum = 0.0; g_ticket = 0u; }

    const float4* v = reinterpret_cast<const float4*>(gt);
    const int n4 = N_TOTAL / 4;
    float m = 0.0f;
    for (int i = blockIdx.x * 256 + threadIdx.x; i < n4; i += MAX_BLOCKS * 256) {
        float4 x = v[i];
        m = fmaxf(m, fmaxf(fmaxf(x.x, x.y), fmaxf(x.z, x.w)));
    }
    #pragma unroll
    for (int o = 16; o; o >>= 1) m = fmaxf(m, __shfl_xor_sync(0xffffffffu, m, o));
    __shared__ float smax[8];
    int lane = threadIdx.x & 31, wid = threadIdx.x >> 5;
    if (lane == 0) smax[wid] = m;
    __syncthreads();
    if (wid == 0) {
        m = (lane < 8) ? smax[lane] : 0.0f;
        #pragma unroll
        for (int o = 4; o; o >>= 1) m = fmaxf(m, __shfl_xor_sync(0xffffffffu, m, o));
        if (lane == 0) g_blockmax[blockIdx.x] = m;
    }
}

// ---------------------------------------------------------------------------
__global__ __launch_bounds__(256, 4)
void ssim_kernel(const float* __restrict__ gt, const float* __restrict__ pred,
                 float* __restrict__ out) {
    __shared__ float4 aos[TH * AOS_STRIDE];   // (s0,s1,s2,s3) per (row, col)
    __shared__ float  s4p[TH * S4_STRIDE];    // s4 plane
    __shared__ float  sred[256];
    __shared__ float  smaxv;

    const int tid = threadIdx.x;
    const int bx = blockIdx.x, by = blockIdx.y, img = blockIdx.z;

    const float* gbase = gt   + img * IMG_ELEMS;
    const float* pbase = pred + img * IMG_ELEMS;

    // ---- Phase A: vertical 7-row box sums, written to shared ----
    if (tid >= 224) {
        int lane = tid - 224;
        float m = 0.0f;
        #pragma unroll
        for (int i = 0; i < MAX_BLOCKS / 32; i++)
            m = fmaxf(m, g_blockmax[lane + 32 * i]);
        #pragma unroll
        for (int o = 16; o; o >>= 1) m = fmaxf(m, __shfl_xor_sync(0xffffffffu, m, o));
        if (lane == 0) smaxv = m;
    } else if (tid < 2 * IN_W) {
        const int h = (tid < IN_W) ? 0 : 1;
        const int c = tid - h * IN_W;
        const int gx = min(bx * TW + c, HW - 1);
        const int rb = by * TH + h * 16;
        const float* gp = gbase + gx;
        const float* pp = pbase + gx;

        float g[7], p[7];
        float s0 = 0.f, s1 = 0.f, s2 = 0.f, s3 = 0.f, s4 = 0.f;
        #pragma unroll
        for (int i = 0; i < 6; i++) {
            int gy = min(rb + i, HW - 1);
            float a = __ldg(gp + gy * HW);
            float b = __ldg(pp + gy * HW);
            g[i] = a; p[i] = b;
            s0 += a; s1 += b;
            s2 = fmaf(a, a, s2); s3 = fmaf(b, b, s3); s4 = fmaf(a, b, s4);
        }
        const int orow = h * 16;
        #pragma unroll
        for (int j = 0; j < 16; j++) {
            int slot = (6 + j) % 7;
            int gy = min(rb + 6 + j, HW - 1);
            float a = __ldg(gp + gy * HW);
            float b = __ldg(pp + gy * HW);
            g[slot] = a; p[slot] = b;
            s0 += a; s1 += b;
            s2 = fmaf(a, a, s2); s3 = fmaf(b, b, s3); s4 = fmaf(a, b, s4);
            aos[(orow + j) * AOS_STRIDE + c] = make_float4(s0, s1, s2, s3);
            s4p[(orow + j) * S4_STRIDE + c] = s4;
            int os = j % 7;
            float ga = g[os], pa = p[os];
            s0 -= ga; s1 -= pa;
            s2 -= ga * ga; s3 -= pa * pa; s4 -= ga * pa;
        }
    }
    __syncthreads();

    // ---- Phase B: horizontal 7-col box sums (vector rolling) + SSIM ----
    const float R  = smaxv;
    const float C1 = (0.01f * R) * (0.01f * R);
    const float C2 = (0.03f * R) * (0.03f * R);
    const float inv = 1.0f / 49.0f;

    const int seg = tid >> 5;
    const int row = tid & 31;
    const int c0  = seg * 8;
    const int abase = row * AOS_STRIDE + c0;
    const int sbase = row * S4_STRIDE  + c0;

    const int oy = PAD + by * TH + row;
    const bool rowvalid = (oy <= HW - 1 - PAD);
    const int ox0 = PAD + bx * TW + c0;

    float4 q[7];
    float  r4[7];
    float4 s = make_float4(0.f, 0.f, 0.f, 0.f);
    float  t4 = 0.f;
    #pragma unroll
    for (int i = 0; i < 6; i++) {
        float4 v = aos[abase + i];
        float  u = s4p[sbase + i];
        q[i] = v; r4[i] = u;
        s.x += v.x; s.y += v.y; s.z += v.z; s.w += v.w;
        t4 += u;
    }

    float local = 0.0f;
    #pragma unroll
    for (int k = 0; k < 8; k++) {
        int slot = (6 + k) % 7;
        float4 v = aos[abase + 6 + k];
        float  u = s4p[sbase + 6 + k];
        q[slot] = v; r4[slot] = u;
        s.x += v.x; s.y += v.y; s.z += v.z; s.w += v.w;
        t4 += u;

        if (rowvalid && (ox0 + k) <= HW - 1 - PAD) {
            float ux = s.x * inv, uy = s.y * inv;
            float uxx = s.z * inv - ux * ux;
            float uyy = s.w * inv - uy * uy;
            float uxy = t4  * inv - ux * uy;
            float vx = COV_NORM * uxx, vy = COV_NORM * uyy, vxy = COV_NORM * uxy;
            float num = (2.0f * ux * uy + C1) * (2.0f * vxy + C2);
            float den = (ux * ux + uy * uy + C1) * (vx + vy + C2);
            local += __fdividef(num, den);
        }

        int os = k % 7;
        float4 w = q[os];
        s.x -= w.x; s.y -= w.y; s.z -= w.z; s.w -= w.w;
        t4 -= r4[os];
    }

    // ---- block reduce + global accumulate + last-block finalize ----
    sred[tid] = local;
    __syncthreads();
    #pragma unroll
    for (int st = 128; st >= 32; st >>= 1) {
        if (tid < st) sred[tid] += sred[tid + st];
        __syncthreads();
    }
    if (tid < 32) {
        float v = sred[tid];
        #pragma unroll
        for (int o = 16; o; o >>= 1) v += __shfl_xor_sync(0xffffffffu, v, o);
        if (tid == 0) {
            atomicAdd(&g_sum, (double)v);
            __threadfence();
            unsigned t = atomicAdd(&g_ticket, 1u);
            if (t == NBLOCKS - 1) {
                double total = atomicAdd(&g_sum, 0.0);
                out[0] = (float)(total / N_OUT);
            }
        }
    }
}

// ---------------------------------------------------------------------------
extern "C" void kernel_launch(void* const* d_in, const int* in_sizes, int n_in,
                              void* d_out, int out_size) {
    const float* gt   = (const float*)d_in[0];
    const float* pred = (const float*)d_in[1];
    float* out = (float*)d_out;

    prep_kernel<<<MAX_BLOCKS, 256>>>(gt);
    dim3 grid(GX_TILES, GY_TILES, B_IMGS);
    ssim_kernel<<<grid, 256>>>(gt, pred, out);
}